// round 5
// baseline (speedup 1.0000x reference)
#include <cuda_runtime.h>

#define DMODEL 1024
#define NHEADS 16
#define DK     64
#define BATCH  4
#define SEQ    2048
#define ROWS   (BATCH*SEQ)    // 8192
#define BH     (BATCH*NHEADS) // 64

// ---------------- scratch ----------------
__device__ float g_q[(size_t)BH*SEQ*DK];
__device__ float g_k[(size_t)BH*SEQ*DK];
__device__ float g_v[(size_t)BH*SEQ*DK];
__device__ float g_ctx[(size_t)ROWS*DMODEL];
__device__ float g_pre[(size_t)ROWS*DMODEL];
__device__ float g_rinv[(size_t)BH*SEQ];

// ---------------- helpers ----------------
__device__ __forceinline__ unsigned f2tf(float f) {
    unsigned u; asm("cvt.rna.tf32.f32 %0, %1;" : "=r"(u) : "f"(f)); return u;
}
__device__ __forceinline__ void mma8(float* c, const unsigned* a, const unsigned* b) {
    asm volatile(
        "mma.sync.aligned.m16n8k8.row.col.f32.tf32.tf32.f32 "
        "{%0,%1,%2,%3}, {%4,%5,%6,%7}, {%8,%9}, {%0,%1,%2,%3};"
        : "+f"(c[0]), "+f"(c[1]), "+f"(c[2]), "+f"(c[3])
        : "r"(a[0]), "r"(a[1]), "r"(a[2]), "r"(a[3]), "r"(b[0]), "r"(b[1]));
}
__device__ __forceinline__ void cpa16(void* s, const void* g) {
    unsigned ss = (unsigned)__cvta_generic_to_shared(s);
    asm volatile("cp.async.cg.shared.global [%0], [%1], 16;" :: "r"(ss), "l"(g));
}
__device__ __forceinline__ void cpcommit() { asm volatile("cp.async.commit_group;" ::: "memory"); }
__device__ __forceinline__ void cpwait1()  { asm volatile("cp.async.wait_group 1;" ::: "memory"); }
__device__ __forceinline__ void cpwait0()  { asm volatile("cp.async.wait_group 0;" ::: "memory"); }

// ---------------- GEMM: C = A(8192x1024) @ W(1024x1024) + bias ----------------
#define GA_STR 36
#define GW_STR 136
#define GEMM_SMEM ((3*128*GA_STR + 3*32*GW_STR)*4)

__global__ __launch_bounds__(256, 2) void gemm_tc(
    const float* __restrict__ A, const float* __restrict__ W,
    const float* __restrict__ bias, const float* __restrict__ resid,
    float* __restrict__ out, int mode, float scale)
{
    extern __shared__ float gsm[];
    float* Af = gsm;                   // 3 x [128][GA_STR]
    float* Wf = Af + 3*128*GA_STR;     // 3 x [32][GW_STR]

    const int tid  = threadIdx.x;
    const int warp = tid >> 5, lane = tid & 31;
    const int g    = lane >> 2, t = lane & 3;
    const int wm   = warp >> 2, wn = warp & 3;
    const int brow = blockIdx.y * 128;
    const int bcol = blockIdx.x * 128;

    auto loadc = [&](int cc) {
        float* Ab = Af + (cc % 3)*128*GA_STR;
        float* Wb = Wf + (cc % 3)*32*GW_STR;
        int kt = cc * 32;
        #pragma unroll
        for (int j = 0; j < 4; j++) {
            int idx = tid + 256*j;
            int r = idx >> 3, jc = idx & 7;
            cpa16(Ab + r*GA_STR + jc*4, A + (size_t)(brow + r)*DMODEL + kt + jc*4);
        }
        #pragma unroll
        for (int j = 0; j < 4; j++) {
            int idx = tid + 256*j;
            int r = idx >> 5, jc = idx & 31;
            cpa16(Wb + r*GW_STR + jc*4, W + (size_t)(kt + r)*DMODEL + bcol + jc*4);
        }
        cpcommit();
    };

    loadc(0); loadc(1);

    float c[4][4][4];
    #pragma unroll
    for (int mt = 0; mt < 4; mt++)
        #pragma unroll
        for (int nt = 0; nt < 4; nt++)
            #pragma unroll
            for (int i = 0; i < 4; i++) c[mt][nt][i] = 0.f;

    for (int cc = 0; cc < 32; cc++) {
        if (cc < 31) cpwait1(); else cpwait0();
        __syncthreads();
        const float* Ab = Af + (cc % 3)*128*GA_STR;
        const float* Wb = Wf + (cc % 3)*32*GW_STR;

        #pragma unroll
        for (int ks = 0; ks < 4; ks++) {
            int k0 = ks*8;
            unsigned bf[4][2];
            #pragma unroll
            for (int nt = 0; nt < 4; nt++) {
                int col = wn*32 + nt*8 + g;
                bf[nt][0] = f2tf(Wb[(k0 + t    )*GW_STR + col]);
                bf[nt][1] = f2tf(Wb[(k0 + t + 4)*GW_STR + col]);
            }
            #pragma unroll
            for (int mt = 0; mt < 4; mt++) {
                int r0 = wm*64 + mt*16 + g;
                unsigned af[4] = {f2tf(Ab[r0*GA_STR + k0 + t]),
                                  f2tf(Ab[(r0+8)*GA_STR + k0 + t]),
                                  f2tf(Ab[r0*GA_STR + k0 + t + 4]),
                                  f2tf(Ab[(r0+8)*GA_STR + k0 + t + 4])};
                #pragma unroll
                for (int nt = 0; nt < 4; nt++) mma8(c[mt][nt], af, bf[nt]);
            }
        }
        if (cc + 2 < 32) loadc(cc + 2);
    }

    #pragma unroll
    for (int mt = 0; mt < 4; mt++)
        #pragma unroll
        for (int nt = 0; nt < 4; nt++)
            #pragma unroll
            for (int i = 0; i < 4; i++) {
                int row = brow + wm*64 + mt*16 + g + ((i >> 1) ? 8 : 0);
                int col = bcol + wn*32 + nt*8 + 2*t + (i & 1);
                float v = c[mt][nt][i] + bias[col];
                if (mode == 0) {
                    v *= scale;
                    int b = row >> 11, s = row & (SEQ-1);
                    int h = col >> 6,  d = col & (DK-1);
                    out[(size_t)((b*NHEADS + h)*SEQ + s)*DK + d] = v;
                } else {
                    v += resid[(size_t)row*DMODEL + col];
                    out[(size_t)row*DMODEL + col] = v;
                }
            }
}

// ---------------- pass A: row sums of exp(QK^T)*mask ----------------
#define SSTR 68
#define SUM_SMEM ((128*SSTR + 3*64*SSTR + SEQ + 512)*4)

__global__ __launch_bounds__(256, 2) void attn_sums(
    const float* __restrict__ Q, const float* __restrict__ K,
    const int* __restrict__ mask, float* __restrict__ rinvg)
{
    extern __shared__ unsigned sm_[];
    unsigned* Qs  = sm_;                        // [128][SSTR] tf32
    float*    Kf  = (float*)(Qs + 128*SSTR);    // 3 x [64][SSTR] fp32
    float*    mskf = Kf + 3*64*SSTR;            // [SEQ]
    float*    red  = mskf + SEQ;                // [4][128]

    const int tid  = threadIdx.x;
    const int warp = tid >> 5, lane = tid & 31;
    const int g    = lane >> 2, t = lane & 3;
    const int wm   = warp >> 2, wn = warp & 3;    // 2 x 4
    const int q0   = blockIdx.x * 128;
    const int bh   = blockIdx.y;
    const int b    = bh >> 4;
    const float* Qb = Q + (size_t)bh*SEQ*DK;
    const float* Kb = K + (size_t)bh*SEQ*DK;

    for (int i = tid; i < SEQ; i += 256) mskf[i] = mask[b*SEQ + i] ? 1.f : 0.f;
    #pragma unroll
    for (int j = 0; j < 8; j++) {
        int idx = tid + 256*j;
        int r = idx >> 4, c4 = (idx & 15)*4;
        float4 v = *(const float4*)(Qb + (size_t)(q0 + r)*DK + c4);
        Qs[r*SSTR + c4 + 0] = f2tf(v.x);
        Qs[r*SSTR + c4 + 1] = f2tf(v.y);
        Qs[r*SSTR + c4 + 2] = f2tf(v.z);
        Qs[r*SSTR + c4 + 3] = f2tf(v.w);
    }

    auto loadk = [&](int cc) {
        float* Kd = Kf + (cc % 3)*64*SSTR;
        int kc = cc * 64;
        #pragma unroll
        for (int j = 0; j < 4; j++) {
            int idx = tid + 256*j;
            int r = idx >> 4, jc = idx & 15;
            cpa16(Kd + r*SSTR + jc*4, Kb + (size_t)(kc + r)*DK + jc*4);
        }
        cpcommit();
    };
    loadk(0); loadk(1);

    float ps[4][2];
    #pragma unroll
    for (int mt = 0; mt < 4; mt++) { ps[mt][0] = 0.f; ps[mt][1] = 0.f; }

    for (int cc = 0; cc < 32; cc++) {
        if (cc < 31) cpwait1(); else cpwait0();
        __syncthreads();
        const float* Kd = Kf + (cc % 3)*64*SSTR;
        int kc = cc * 64;

        float acc[4][2][4];
        #pragma unroll
        for (int mt = 0; mt < 4; mt++)
            #pragma unroll
            for (int nt = 0; nt < 2; nt++)
                #pragma unroll
                for (int i = 0; i < 4; i++) acc[mt][nt][i] = 0.f;

        #pragma unroll
        for (int ks = 0; ks < 8; ks++) {
            int k0 = ks*8;
            unsigned bf[2][2];
            #pragma unroll
            for (int nt = 0; nt < 2; nt++) {
                int col = wn*16 + nt*8 + g;
                bf[nt][0] = f2tf(Kd[col*SSTR + k0 + t]);
                bf[nt][1] = f2tf(Kd[col*SSTR + k0 + t + 4]);
            }
            #pragma unroll
            for (int mt = 0; mt < 4; mt++) {
                int r0 = wm*64 + mt*16 + g;
                unsigned af[4] = {Qs[r0*SSTR + k0 + t], Qs[(r0+8)*SSTR + k0 + t],
                                  Qs[r0*SSTR + k0 + t + 4], Qs[(r0+8)*SSTR + k0 + t + 4]};
                #pragma unroll
                for (int nt = 0; nt < 2; nt++) mma8(acc[mt][nt], af, bf[nt]);
            }
        }
        #pragma unroll
        for (int mt = 0; mt < 4; mt++)
            #pragma unroll
            for (int nt = 0; nt < 2; nt++)
                #pragma unroll
                for (int half = 0; half < 2; half++) {
                    int col = kc + wn*16 + nt*8 + 2*t;
                    ps[mt][half] += __expf(acc[mt][nt][half*2 + 0]) * mskf[col]
                                  + __expf(acc[mt][nt][half*2 + 1]) * mskf[col + 1];
                }
        if (cc + 2 < 32) loadk(cc + 2);
    }

    #pragma unroll
    for (int mt = 0; mt < 4; mt++)
        #pragma unroll
        for (int half = 0; half < 2; half++) {
            float v = ps[mt][half];
            v += __shfl_xor_sync(0xffffffffu, v, 1);
            v += __shfl_xor_sync(0xffffffffu, v, 2);
            if (t == 0) red[wn*128 + wm*64 + mt*16 + g + half*8] = v;
        }
    __syncthreads();
    if (tid < 128) {
        float s = red[tid] + red[128 + tid] + red[256 + tid] + red[384 + tid];
        rinvg[(size_t)bh*SEQ + q0 + tid] = 1.0f / s;
    }
}

// ---------------- pass B: recompute QK, normalize, write att, PV ----------------
#define FSTR  68
#define VSTRF 72
#define FUS_SMEM ((128*FSTR + 3*64*FSTR + 3*64*VSTRF + 128*FSTR + SEQ + 128)*4)

__global__ __launch_bounds__(512, 1) void attn_fused(
    const float* __restrict__ Q, const float* __restrict__ K, const float* __restrict__ V,
    const int* __restrict__ mask, const float* __restrict__ rinvg,
    float* __restrict__ ctx, float* __restrict__ attout)
{
    extern __shared__ unsigned sm_[];
    unsigned* Qs  = sm_;                         // [128][FSTR] tf32
    float*    Kf  = (float*)(Qs + 128*FSTR);     // 3 x [64][FSTR]
    float*    Vf  = Kf + 3*64*FSTR;              // 3 x [64][VSTRF]
    float*    Es  = Vf + 3*64*VSTRF;             // [128][FSTR]
    float*    mskf = Es + 128*FSTR;              // [SEQ]
    float*    rinv = mskf + SEQ;                 // [128]

    const int tid  = threadIdx.x;
    const int warp = tid >> 5, lane = tid & 31;
    const int g    = lane >> 2, t = lane & 3;
    const int wm   = warp >> 2, wn = warp & 3;    // 4 x 4
    const int q0   = blockIdx.x * 128;
    const int bh   = blockIdx.y;
    const int b    = bh >> 4, h = bh & 15;
    const float* Qb = Q + (size_t)bh*SEQ*DK;
    const float* Kb = K + (size_t)bh*SEQ*DK;
    const float* Vb = V + (size_t)bh*SEQ*DK;

    for (int i = tid; i < SEQ; i += 512) mskf[i] = mask[b*SEQ + i] ? 1.f : 0.f;
    if (tid < 128) rinv[tid] = rinvg[(size_t)bh*SEQ + q0 + tid];
    #pragma unroll
    for (int j = 0; j < 4; j++) {
        int idx = tid + 512*j;
        int r = idx >> 4, c4 = (idx & 15)*4;
        float4 v = *(const float4*)(Qb + (size_t)(q0 + r)*DK + c4);
        Qs[r*FSTR + c4 + 0] = f2tf(v.x);
        Qs[r*FSTR + c4 + 1] = f2tf(v.y);
        Qs[r*FSTR + c4 + 2] = f2tf(v.z);
        Qs[r*FSTR + c4 + 3] = f2tf(v.w);
    }

    auto loadkv = [&](int cc) {
        int kc = cc * 64, buf = cc % 3;
        float* Kd = Kf + buf*64*FSTR;
        float* Vd = Vf + buf*64*VSTRF;
        #pragma unroll
        for (int j = 0; j < 2; j++) {
            int idx = tid + 512*j;
            int r = idx >> 4, jc = idx & 15;
            cpa16(Kd + r*FSTR + jc*4, Kb + (size_t)(kc + r)*DK + jc*4);
        }
        #pragma unroll
        for (int j = 0; j < 2; j++) {
            int idx = tid + 512*j;
            int r = idx >> 4, jc = idx & 15;
            cpa16(Vd + r*VSTRF + jc*4, Vb + (size_t)(kc + r)*DK + jc*4);
        }
        cpcommit();
    };
    loadkv(0); loadkv(1);

    float d[2][2][4];
    #pragma unroll
    for (int mt = 0; mt < 2; mt++)
        #pragma unroll
        for (int nt = 0; nt < 2; nt++)
            #pragma unroll
            for (int i = 0; i < 4; i++) d[mt][nt][i] = 0.f;

    for (int cc = 0; cc < 32; cc++) {
        if (cc < 31) cpwait1(); else cpwait0();
        __syncthreads();
        const float* Kd = Kf + (cc % 3)*64*FSTR;
        const float* Vd = Vf + (cc % 3)*64*VSTRF;
        int kc = cc * 64;

        // ---- QK ----
        float s[2][2][4];
        #pragma unroll
        for (int mt = 0; mt < 2; mt++)
            #pragma unroll
            for (int nt = 0; nt < 2; nt++)
                #pragma unroll
                for (int i = 0; i < 4; i++) s[mt][nt][i] = 0.f;

        #pragma unroll
        for (int ks = 0; ks < 8; ks++) {
            int k0 = ks*8;
            unsigned bf[2][2];
            #pragma unroll
            for (int nt = 0; nt < 2; nt++) {
                int col = wn*16 + nt*8 + g;
                bf[nt][0] = f2tf(Kd[col*FSTR + k0 + t]);
                bf[nt][1] = f2tf(Kd[col*FSTR + k0 + t + 4]);
            }
            #pragma unroll
            for (int mt = 0; mt < 2; mt++) {
                int r0 = wm*32 + mt*16 + g;
                unsigned af[4] = {Qs[r0*FSTR + k0 + t], Qs[(r0+8)*FSTR + k0 + t],
                                  Qs[r0*FSTR + k0 + t + 4], Qs[(r0+8)*FSTR + k0 + t + 4]};
                #pragma unroll
                for (int nt = 0; nt < 2; nt++) mma8(s[mt][nt], af, bf[nt]);
            }
        }

        // ---- epilogue: normalized exp into Es ----
        #pragma unroll
        for (int mt = 0; mt < 2; mt++)
            #pragma unroll
            for (int nt = 0; nt < 2; nt++)
                #pragma unroll
                for (int half = 0; half < 2; half++) {
                    int row = wm*32 + mt*16 + g + half*8;
                    int col = wn*16 + nt*8 + 2*t;
                    float iv = rinv[row];
                    float e0 = __expf(s[mt][nt][half*2 + 0]) * mskf[kc + col]     * iv;
                    float e1 = __expf(s[mt][nt][half*2 + 1]) * mskf[kc + col + 1] * iv;
                    *(float2*)(Es + row*FSTR + col) = make_float2(e0, e1);
                }
        __syncthreads();

        // ---- att write ----
        #pragma unroll
        for (int j = 0; j < 4; j++) {
            int idx = tid + 512*j;
            int r = idx >> 4, c4 = (idx & 15)*4;
            float4 v = *(const float4*)(Es + r*FSTR + c4);
            *(float4*)(attout + ((size_t)bh*SEQ + q0 + r)*SEQ + kc + c4) = v;
        }

        // ---- PV ----
        #pragma unroll
        for (int ks = 0; ks < 8; ks++) {
            int k0 = ks*8;
            unsigned bf[2][2];
            #pragma unroll
            for (int nt = 0; nt < 2; nt++) {
                int col = wn*16 + nt*8 + g;
                bf[nt][0] = f2tf(Vd[(k0 + t)*VSTRF + col]);
                bf[nt][1] = f2tf(Vd[(k0 + t + 4)*VSTRF + col]);
            }
            #pragma unroll
            for (int mt = 0; mt < 2; mt++) {
                int r0 = wm*32 + mt*16 + g;
                unsigned af[4] = {f2tf(Es[r0*FSTR + k0 + t]),
                                  f2tf(Es[(r0+8)*FSTR + k0 + t]),
                                  f2tf(Es[r0*FSTR + k0 + t + 4]),
                                  f2tf(Es[(r0+8)*FSTR + k0 + t + 4])};
                #pragma unroll
                for (int nt = 0; nt < 2; nt++) mma8(d[mt][nt], af, bf[nt]);
            }
        }
        if (cc + 2 < 32) loadkv(cc + 2);
    }

    #pragma unroll
    for (int mt = 0; mt < 2; mt++)
        #pragma unroll
        for (int nt = 0; nt < 2; nt++)
            #pragma unroll
            for (int half = 0; half < 2; half++) {
                int row = wm*32 + mt*16 + g + half*8;
                int col = wn*16 + nt*8 + 2*t;
                float2 ov = make_float2(d[mt][nt][half*2 + 0], d[mt][nt][half*2 + 1]);
                *(float2*)(ctx + (size_t)(b*SEQ + q0 + row)*DMODEL + h*DK + col) = ov;
            }
}

// ---------------- LayerNorm ----------------
__global__ __launch_bounds__(256) void ln_kernel(
    const float* __restrict__ pre, const float* __restrict__ gamma,
    const float* __restrict__ beta, float* __restrict__ out)
{
    const int tid = threadIdx.x;
    const int row = blockIdx.x;
    float4 v = ((const float4*)(pre + (size_t)row*DMODEL))[tid];
    float s  = v.x + v.y + v.z + v.w;
    float s2 = v.x*v.x + v.y*v.y + v.z*v.z + v.w*v.w;
    #pragma unroll
    for (int o = 16; o > 0; o >>= 1) {
        s  += __shfl_xor_sync(0xffffffffu, s,  o);
        s2 += __shfl_xor_sync(0xffffffffu, s2, o);
    }
    __shared__ float ws[8], ws2[8];
    __shared__ float mu_s, r_s;
    if ((tid & 31) == 0) { ws[tid >> 5] = s; ws2[tid >> 5] = s2; }
    __syncthreads();
    if (tid == 0) {
        float tt = 0.f, t2 = 0.f;
        #pragma unroll
        for (int i = 0; i < 8; i++) { tt += ws[i]; t2 += ws2[i]; }
        float mu  = tt * (1.0f/DMODEL);
        float var = t2 * (1.0f/DMODEL) - mu*mu;
        mu_s = mu;
        r_s  = rsqrtf(var + 1e-5f);
    }
    __syncthreads();
    float mu = mu_s, r = r_s;
    float4 gm = ((const float4*)gamma)[tid];
    float4 be = ((const float4*)beta)[tid];
    float4 o;
    o.x = (v.x - mu)*r*gm.x + be.x;
    o.y = (v.y - mu)*r*gm.y + be.y;
    o.z = (v.z - mu)*r*gm.z + be.z;
    o.w = (v.w - mu)*r*gm.w + be.w;
    ((float4*)(out + (size_t)row*DMODEL))[tid] = o;
}

// ---------------- launch ----------------
extern "C" void kernel_launch(void* const* d_in, const int* in_sizes, int n_in,
                              void* d_out, int out_size)
{
    const float* x     = (const float*)d_in[0];
    const int*   mask  = (const int*)  d_in[1];
    const float* Wq    = (const float*)d_in[2];
    const float* bq    = (const float*)d_in[3];
    const float* Wk    = (const float*)d_in[4];
    const float* bk    = (const float*)d_in[5];
    const float* Wv    = (const float*)d_in[6];
    const float* bv    = (const float*)d_in[7];
    const float* Wo    = (const float*)d_in[8];
    const float* bo    = (const float*)d_in[9];
    const float* gamma = (const float*)d_in[10];
    const float* beta  = (const float*)d_in[11];
    float* out = (float*)d_out;

    void *pq, *pk, *pv, *pctx, *ppre, *pri;
    cudaGetSymbolAddress(&pq,   g_q);
    cudaGetSymbolAddress(&pk,   g_k);
    cudaGetSymbolAddress(&pv,   g_v);
    cudaGetSymbolAddress(&pctx, g_ctx);
    cudaGetSymbolAddress(&ppre, g_pre);
    cudaGetSymbolAddress(&pri,  g_rinv);

    const long long OUT_ELEMS = (long long)ROWS * DMODEL;
    float* attout = out + OUT_ELEMS;

    cudaFuncSetAttribute(gemm_tc,    cudaFuncAttributeMaxDynamicSharedMemorySize, GEMM_SMEM);
    cudaFuncSetAttribute(attn_sums,  cudaFuncAttributeMaxDynamicSharedMemorySize, SUM_SMEM);
    cudaFuncSetAttribute(attn_fused, cudaFuncAttributeMaxDynamicSharedMemorySize, FUS_SMEM);

    dim3 gg(DMODEL/128, ROWS/128);
    gemm_tc<<<gg, 256, GEMM_SMEM>>>(x, Wq, bq, nullptr, (float*)pq, 0, 0.125f);
    gemm_tc<<<gg, 256, GEMM_SMEM>>>(x, Wk, bk, nullptr, (float*)pk, 0, 1.0f);
    gemm_tc<<<gg, 256, GEMM_SMEM>>>(x, Wv, bv, nullptr, (float*)pv, 0, 1.0f);

    attn_sums<<<dim3(SEQ/128, BH), 256, SUM_SMEM>>>(
        (const float*)pq, (const float*)pk, mask, (float*)pri);
    attn_fused<<<dim3(SEQ/128, BH), 512, FUS_SMEM>>>(
        (const float*)pq, (const float*)pk, (const float*)pv, mask,
        (const float*)pri, (float*)pctx, attout);

    gemm_tc<<<gg, 256, GEMM_SMEM>>>((const float*)pctx, Wo, bo, x, (float*)ppre, 1, 1.0f);
    ln_kernel<<<ROWS, 256>>>((const float*)ppre, gamma, beta, out);
}